// round 1
// baseline (speedup 1.0000x reference)
#include <cuda_runtime.h>

#define N_NODES 100000
#define E_EDGES 1600000
#define HDIM 48

// Persistent scratch (no allocations allowed).
__device__ float g_h[N_NODES * HDIM];    // current node features (gather source)
__device__ float g_agg[N_NODES * HDIM];  // self + neighbor sum (MLP input)

// ---------------------------------------------------------------------------
// init: h = agg = x
// ---------------------------------------------------------------------------
__global__ void init_kernel(const float* __restrict__ x) {
    int i = blockIdx.x * blockDim.x + threadIdx.x;
    const int total = N_NODES * HDIM / 4;
    if (i < total) {
        float4 v = ((const float4*)x)[i];
        ((float4*)g_h)[i] = v;
        ((float4*)g_agg)[i] = v;
    }
}

// ---------------------------------------------------------------------------
// scatter: agg[dst] += h[src] over all edges.
// One thread per half-edge (24 features = 6 float4 loads + 24 atomics).
// ---------------------------------------------------------------------------
__global__ void scatter_kernel(const int* __restrict__ ei) {
    int idx = blockIdx.x * blockDim.x + threadIdx.x;
    if (idx >= 2 * E_EDGES) return;
    int e    = idx >> 1;
    int half = idx & 1;
    int src = ei[e];
    int dst = ei[E_EDGES + e];
    const float4* __restrict__ hp = (const float4*)(g_h + src * HDIM) + half * 6;
    float* __restrict__ ap = g_agg + dst * HDIM + half * 24;
    float4 v[6];
#pragma unroll
    for (int c = 0; c < 6; c++) v[c] = hp[c];  // front-batched: MLP=6
#pragma unroll
    for (int c = 0; c < 6; c++) {
        atomicAdd(ap + 4 * c + 0, v[c].x);
        atomicAdd(ap + 4 * c + 1, v[c].y);
        atomicAdd(ap + 4 * c + 2, v[c].z);
        atomicAdd(ap + 4 * c + 3, v[c].w);
    }
}

// ---------------------------------------------------------------------------
// Fused 2-layer MLP. Reads g_agg row, computes
//   y = relu(x @ W1 + b1);  z = (relu?)(y @ W2 + b2)
// DO = out dim of layer 2. WRITE_STATE: write z to g_h AND g_agg (conv layers).
// Otherwise write to `out` (head). W in shared, x/y in registers,
// float4 W loads -> 1 LDS.128 per 4 FFMA.
// ---------------------------------------------------------------------------
template <int DO, bool RELU2, bool WRITE_STATE>
__global__ void mlp_kernel(const float* __restrict__ W1, const float* __restrict__ b1,
                           const float* __restrict__ W2, const float* __restrict__ b2,
                           float* __restrict__ out) {
    __shared__ float sW1[HDIM * HDIM];
    __shared__ float sW2[HDIM * DO];
    __shared__ float sb1[HDIM];
    __shared__ float sb2[DO];

    // Cooperative shared loads
    for (int i = threadIdx.x; i < HDIM * HDIM; i += blockDim.x) sW1[i] = W1[i];
    for (int i = threadIdx.x; i < HDIM * DO;  i += blockDim.x) sW2[i] = W2[i];
    if (threadIdx.x < HDIM) sb1[threadIdx.x] = b1[threadIdx.x];
    if (threadIdx.x < DO)   sb2[threadIdx.x] = b2[threadIdx.x];
    __syncthreads();

    int n = blockIdx.x * blockDim.x + threadIdx.x;
    if (n >= N_NODES) return;

    float x[HDIM];
    {
        const float4* __restrict__ inp = (const float4*)(g_agg + n * HDIM);
#pragma unroll
        for (int c = 0; c < HDIM / 4; c++) {
            float4 v = inp[c];
            x[4 * c + 0] = v.x; x[4 * c + 1] = v.y;
            x[4 * c + 2] = v.z; x[4 * c + 3] = v.w;
        }
    }

    // Layer 1: 48 -> 48, relu
    float y[HDIM];
#pragma unroll
    for (int jt = 0; jt < HDIM / 4; jt++) {
        float4 acc = ((const float4*)sb1)[jt];
#pragma unroll
        for (int k = 0; k < HDIM; k++) {
            float4 w = ((const float4*)sW1)[k * (HDIM / 4) + jt];
            acc.x += x[k] * w.x;
            acc.y += x[k] * w.y;
            acc.z += x[k] * w.z;
            acc.w += x[k] * w.w;
        }
        y[4 * jt + 0] = fmaxf(acc.x, 0.f);
        y[4 * jt + 1] = fmaxf(acc.y, 0.f);
        y[4 * jt + 2] = fmaxf(acc.z, 0.f);
        y[4 * jt + 3] = fmaxf(acc.w, 0.f);
    }

    // Layer 2: 48 -> DO
#pragma unroll
    for (int jt = 0; jt < DO / 4; jt++) {
        float4 acc = ((const float4*)sb2)[jt];
#pragma unroll
        for (int k = 0; k < HDIM; k++) {
            float4 w = ((const float4*)sW2)[k * (DO / 4) + jt];
            acc.x += y[k] * w.x;
            acc.y += y[k] * w.y;
            acc.z += y[k] * w.z;
            acc.w += y[k] * w.w;
        }
        if (RELU2) {
            acc.x = fmaxf(acc.x, 0.f); acc.y = fmaxf(acc.y, 0.f);
            acc.z = fmaxf(acc.z, 0.f); acc.w = fmaxf(acc.w, 0.f);
        }
        if (WRITE_STATE) {
            ((float4*)(g_h   + n * HDIM))[jt] = acc;
            ((float4*)(g_agg + n * HDIM))[jt] = acc;
        } else {
            ((float4*)(out + n * DO))[jt] = acc;
        }
    }
}

// ---------------------------------------------------------------------------
extern "C" void kernel_launch(void* const* d_in, const int* in_sizes, int n_in,
                              void* d_out, int out_size) {
    const float* x   = (const float*)d_in[0];
    const int*   ei  = (const int*)d_in[1];
    const float* w11 = (const float*)d_in[2];
    const float* b11 = (const float*)d_in[3];
    const float* w12 = (const float*)d_in[4];
    const float* b12 = (const float*)d_in[5];
    const float* w21 = (const float*)d_in[6];
    const float* b21 = (const float*)d_in[7];
    const float* w22 = (const float*)d_in[8];
    const float* b22 = (const float*)d_in[9];
    const float* w31 = (const float*)d_in[10];
    const float* b31 = (const float*)d_in[11];
    const float* w32 = (const float*)d_in[12];
    const float* b32 = (const float*)d_in[13];
    const float* wf1 = (const float*)d_in[14];
    const float* bf1 = (const float*)d_in[15];
    const float* wf2 = (const float*)d_in[16];
    const float* bf2 = (const float*)d_in[17];
    float* out = (float*)d_out;

    const int TPB = 256;
    const int init_grid    = (N_NODES * HDIM / 4 + TPB - 1) / TPB;
    const int scatter_grid = (2 * E_EDGES + TPB - 1) / TPB;
    const int node_grid    = (N_NODES + TPB - 1) / TPB;

    init_kernel<<<init_grid, TPB>>>(x);

    // Conv 1
    scatter_kernel<<<scatter_grid, TPB>>>(ei);
    mlp_kernel<HDIM, true, true><<<node_grid, TPB>>>(w11, b11, w12, b12, nullptr);
    // Conv 2
    scatter_kernel<<<scatter_grid, TPB>>>(ei);
    mlp_kernel<HDIM, true, true><<<node_grid, TPB>>>(w21, b21, w22, b22, nullptr);
    // Conv 3
    scatter_kernel<<<scatter_grid, TPB>>>(ei);
    mlp_kernel<HDIM, true, true><<<node_grid, TPB>>>(w31, b31, w32, b32, nullptr);
    // Head: Linear -> ReLU -> Linear (no final relu), writes d_out
    mlp_kernel<16, false, false><<<node_grid, TPB>>>(wf1, bf1, wf2, bf2, out);

    (void)in_sizes; (void)n_in; (void)out_size;
}

// round 2
// speedup vs baseline: 4.0951x; 4.0951x over previous
#include <cuda_runtime.h>

#define N_NODES 100000
#define E_EDGES 1600000
#define HDIM 48
#define NQ (HDIM / 4)   // 12 float4 columns
#define CAP 96          // max tracked in-degree (Poisson(16): P(>50) ~ 1e-11)

// Persistent scratch (no allocations allowed).
__device__ float g_h[N_NODES * HDIM];        // current node features
__device__ float g_agg[N_NODES * HDIM];      // self + neighbor sum (MLP input)
__device__ int   g_count[N_NODES];           // in-degree counters
__device__ int   g_slots[N_NODES * CAP];     // per-dst source lists

// ---------------------------------------------------------------------------
// init: h = x ; count = 0
// ---------------------------------------------------------------------------
__global__ void init_kernel(const float* __restrict__ x) {
    int i = blockIdx.x * blockDim.x + threadIdx.x;
    const int total = N_NODES * NQ;
    if (i < total) ((float4*)g_h)[i] = ((const float4*)x)[i];
    if (i < N_NODES) g_count[i] = 0;
}

// ---------------------------------------------------------------------------
// build adjacency: bin src indices by dst (order within a bin is irrelevant
// for a sum). One int atomic per edge instead of 48 float atomics.
// ---------------------------------------------------------------------------
__global__ void build_kernel(const int* __restrict__ ei) {
    int e = blockIdx.x * blockDim.x + threadIdx.x;
    if (e >= E_EDGES) return;
    int src = ei[e];
    int dst = ei[E_EDGES + e];
    int pos = atomicAdd(&g_count[dst], 1);
    if (pos < CAP) g_slots[dst * CAP + pos] = src;
}

// ---------------------------------------------------------------------------
// gather: agg[n] = h[n] + sum_{s in adj(n)} h[s]
// One thread per (node, float4 column). Lanes covering one node read
// consecutive float4s of each neighbor row -> coalesced 192B bursts, all
// L2-resident. Slot loads 4-way batched for MLP.
// ---------------------------------------------------------------------------
__global__ void gather_kernel() {
    int idx = blockIdx.x * blockDim.x + threadIdx.x;
    if (idx >= N_NODES * NQ) return;
    int n = idx / NQ;
    int c = idx % NQ;

    const float4* __restrict__ h4 = (const float4*)g_h;
    float4 acc = h4[n * NQ + c];                       // self term (eps=0 GIN)
    int deg = min(g_count[n], CAP);
    const int* __restrict__ sl = g_slots + n * CAP;

    int i = 0;
    for (; i + 4 <= deg; i += 4) {
        int s0 = sl[i], s1 = sl[i + 1], s2 = sl[i + 2], s3 = sl[i + 3];
        float4 v0 = h4[s0 * NQ + c];
        float4 v1 = h4[s1 * NQ + c];
        float4 v2 = h4[s2 * NQ + c];
        float4 v3 = h4[s3 * NQ + c];
        acc.x += (v0.x + v1.x) + (v2.x + v3.x);
        acc.y += (v0.y + v1.y) + (v2.y + v3.y);
        acc.z += (v0.z + v1.z) + (v2.z + v3.z);
        acc.w += (v0.w + v1.w) + (v2.w + v3.w);
    }
    for (; i < deg; i++) {
        int s = sl[i];
        float4 v = h4[s * NQ + c];
        acc.x += v.x; acc.y += v.y; acc.z += v.z; acc.w += v.w;
    }
    ((float4*)g_agg)[n * NQ + c] = acc;
}

// ---------------------------------------------------------------------------
// Fused 2-layer MLP.
//   CONV=true : input g_agg, output g_h (relu both layers)
//   CONV=false: input g_h,  output `out` (head: Linear->ReLU->Linear)
// W in shared (broadcast reads), x/y in registers, float4 W loads.
// ---------------------------------------------------------------------------
template <int DO, bool RELU2, bool CONV>
__global__ void mlp_kernel(const float* __restrict__ W1, const float* __restrict__ b1,
                           const float* __restrict__ W2, const float* __restrict__ b2,
                           float* __restrict__ out) {
    __shared__ float sW1[HDIM * HDIM];
    __shared__ float sW2[HDIM * DO];
    __shared__ float sb1[HDIM];
    __shared__ float sb2[DO];

    for (int i = threadIdx.x; i < HDIM * HDIM; i += blockDim.x) sW1[i] = W1[i];
    for (int i = threadIdx.x; i < HDIM * DO;  i += blockDim.x) sW2[i] = W2[i];
    if (threadIdx.x < HDIM) sb1[threadIdx.x] = b1[threadIdx.x];
    if (threadIdx.x < DO)   sb2[threadIdx.x] = b2[threadIdx.x];
    __syncthreads();

    int n = blockIdx.x * blockDim.x + threadIdx.x;
    if (n >= N_NODES) return;

    const float* __restrict__ input = CONV ? g_agg : g_h;

    float x[HDIM];
    {
        const float4* __restrict__ inp = (const float4*)(input + n * HDIM);
#pragma unroll
        for (int c = 0; c < NQ; c++) {
            float4 v = inp[c];
            x[4 * c + 0] = v.x; x[4 * c + 1] = v.y;
            x[4 * c + 2] = v.z; x[4 * c + 3] = v.w;
        }
    }

    // Layer 1: 48 -> 48, relu
    float y[HDIM];
#pragma unroll
    for (int jt = 0; jt < NQ; jt++) {
        float4 acc = ((const float4*)sb1)[jt];
#pragma unroll
        for (int k = 0; k < HDIM; k++) {
            float4 w = ((const float4*)sW1)[k * NQ + jt];
            acc.x += x[k] * w.x;
            acc.y += x[k] * w.y;
            acc.z += x[k] * w.z;
            acc.w += x[k] * w.w;
        }
        y[4 * jt + 0] = fmaxf(acc.x, 0.f);
        y[4 * jt + 1] = fmaxf(acc.y, 0.f);
        y[4 * jt + 2] = fmaxf(acc.z, 0.f);
        y[4 * jt + 3] = fmaxf(acc.w, 0.f);
    }

    // Layer 2: 48 -> DO
#pragma unroll
    for (int jt = 0; jt < DO / 4; jt++) {
        float4 acc = ((const float4*)sb2)[jt];
#pragma unroll
        for (int k = 0; k < HDIM; k++) {
            float4 w = ((const float4*)sW2)[k * (DO / 4) + jt];
            acc.x += y[k] * w.x;
            acc.y += y[k] * w.y;
            acc.z += y[k] * w.z;
            acc.w += y[k] * w.w;
        }
        if (RELU2) {
            acc.x = fmaxf(acc.x, 0.f); acc.y = fmaxf(acc.y, 0.f);
            acc.z = fmaxf(acc.z, 0.f); acc.w = fmaxf(acc.w, 0.f);
        }
        if (CONV) {
            ((float4*)(g_h + n * HDIM))[jt] = acc;
        } else {
            ((float4*)(out + n * DO))[jt] = acc;
        }
    }
}

// ---------------------------------------------------------------------------
extern "C" void kernel_launch(void* const* d_in, const int* in_sizes, int n_in,
                              void* d_out, int out_size) {
    const float* x   = (const float*)d_in[0];
    const int*   ei  = (const int*)d_in[1];
    const float* w11 = (const float*)d_in[2];
    const float* b11 = (const float*)d_in[3];
    const float* w12 = (const float*)d_in[4];
    const float* b12 = (const float*)d_in[5];
    const float* w21 = (const float*)d_in[6];
    const float* b21 = (const float*)d_in[7];
    const float* w22 = (const float*)d_in[8];
    const float* b22 = (const float*)d_in[9];
    const float* w31 = (const float*)d_in[10];
    const float* b31 = (const float*)d_in[11];
    const float* w32 = (const float*)d_in[12];
    const float* b32 = (const float*)d_in[13];
    const float* wf1 = (const float*)d_in[14];
    const float* bf1 = (const float*)d_in[15];
    const float* wf2 = (const float*)d_in[16];
    const float* bf2 = (const float*)d_in[17];
    float* out = (float*)d_out;

    const int TPB = 256;
    const int init_grid   = (N_NODES * NQ + TPB - 1) / TPB;
    const int build_grid  = (E_EDGES + TPB - 1) / TPB;
    const int gather_grid = (N_NODES * NQ + TPB - 1) / TPB;
    const int node_grid   = (N_NODES + TPB - 1) / TPB;

    init_kernel<<<init_grid, TPB>>>(x);
    build_kernel<<<build_grid, TPB>>>(ei);   // adjacency built ONCE, reused x3

    // Conv 1
    gather_kernel<<<gather_grid, TPB>>>();
    mlp_kernel<HDIM, true, true><<<node_grid, TPB>>>(w11, b11, w12, b12, nullptr);
    // Conv 2
    gather_kernel<<<gather_grid, TPB>>>();
    mlp_kernel<HDIM, true, true><<<node_grid, TPB>>>(w21, b21, w22, b22, nullptr);
    // Conv 3
    gather_kernel<<<gather_grid, TPB>>>();
    mlp_kernel<HDIM, true, true><<<node_grid, TPB>>>(w31, b31, w32, b32, nullptr);
    // Head: Linear -> ReLU -> Linear (no final relu), writes d_out
    mlp_kernel<16, false, false><<<node_grid, TPB>>>(wf1, bf1, wf2, bf2, out);

    (void)in_sizes; (void)n_in; (void)out_size;
}

// round 3
// speedup vs baseline: 5.1703x; 1.2625x over previous
#include <cuda_runtime.h>

#define N_NODES 100000
#define E_EDGES 1600000
#define HDIM 48
#define NQ (HDIM / 4)   // 12 float4 columns
#define CAP 96          // max tracked in-degree (Poisson(16): P(>50) ~ 1e-11)

#define TM 128          // node tile per block
#define SXS 132         // padded shared tile stride (128 + 4)
#define MLP_THREADS 192 // 16 M-tiles x 12 N-tiles

// Persistent scratch (no allocations allowed).
__device__ float g_h[N_NODES * HDIM];        // current node features
__device__ float g_agg[N_NODES * HDIM];      // self + neighbor sum (MLP input)
__device__ int   g_count[N_NODES];           // in-degree counters
__device__ int   g_slots[N_NODES * CAP];     // per-dst source lists

// ---------------------------------------------------------------------------
// init: h = x ; count = 0
// ---------------------------------------------------------------------------
__global__ void init_kernel(const float* __restrict__ x) {
    int i = blockIdx.x * blockDim.x + threadIdx.x;
    const int total = N_NODES * NQ;
    if (i < total) ((float4*)g_h)[i] = ((const float4*)x)[i];
    if (i < N_NODES) g_count[i] = 0;
}

// ---------------------------------------------------------------------------
// build adjacency: bin src indices by dst. One int atomic per edge.
// ---------------------------------------------------------------------------
__global__ void build_kernel(const int* __restrict__ ei) {
    int e = blockIdx.x * blockDim.x + threadIdx.x;
    if (e >= E_EDGES) return;
    int src = ei[e];
    int dst = ei[E_EDGES + e];
    int pos = atomicAdd(&g_count[dst], 1);
    if (pos < CAP) g_slots[dst * CAP + pos] = src;
}

// ---------------------------------------------------------------------------
// gather: agg[n] = h[n] + sum_{s in adj(n)} h[s]    (near L2 roofline)
// ---------------------------------------------------------------------------
__global__ void gather_kernel() {
    int idx = blockIdx.x * blockDim.x + threadIdx.x;
    if (idx >= N_NODES * NQ) return;
    int n = idx / NQ;
    int c = idx % NQ;

    const float4* __restrict__ h4 = (const float4*)g_h;
    float4 acc = h4[n * NQ + c];
    int deg = min(g_count[n], CAP);
    const int* __restrict__ sl = g_slots + n * CAP;

    int i = 0;
    for (; i + 4 <= deg; i += 4) {
        int s0 = sl[i], s1 = sl[i + 1], s2 = sl[i + 2], s3 = sl[i + 3];
        float4 v0 = h4[s0 * NQ + c];
        float4 v1 = h4[s1 * NQ + c];
        float4 v2 = h4[s2 * NQ + c];
        float4 v3 = h4[s3 * NQ + c];
        acc.x += (v0.x + v1.x) + (v2.x + v3.x);
        acc.y += (v0.y + v1.y) + (v2.y + v3.y);
        acc.z += (v0.z + v1.z) + (v2.z + v3.z);
        acc.w += (v0.w + v1.w) + (v2.w + v3.w);
    }
    for (; i < deg; i++) {
        int s = sl[i];
        float4 v = h4[s * NQ + c];
        acc.x += v.x; acc.y += v.y; acc.z += v.z; acc.w += v.w;
    }
    ((float4*)g_agg)[n * NQ + c] = acc;
}

// ---------------------------------------------------------------------------
// Tiled GEMM building blocks. sT holds a transposed tile: sT[feat][node],
// stride SXS. One 48->48 layer: each thread (mt = tid/12, nt = tid%12)
// computes an 8M x 4N micro-tile; A from shared (2x LDS.128), B (weights)
// from global via L1-resident LDG.128.  32 FFMA per 3 load instructions.
// ---------------------------------------------------------------------------
__device__ __forceinline__ void layer48_to_smem(
    float* sT, const float* __restrict__ W, const float* __restrict__ B,
    int tid, bool relu) {
    int mt = tid / 12, nt = tid % 12;
    int m0 = mt * 8;
    const float4* __restrict__ W4 = (const float4*)W;
    float4 bias = ((const float4*)B)[nt];

    float acc[8][4];
#pragma unroll
    for (int m = 0; m < 8; m++) {
        acc[m][0] = bias.x; acc[m][1] = bias.y;
        acc[m][2] = bias.z; acc[m][3] = bias.w;
    }
#pragma unroll 8
    for (int k = 0; k < HDIM; k++) {
        float4 b4 = W4[k * NQ + nt];
        float4 a0 = *(const float4*)&sT[k * SXS + m0];
        float4 a1 = *(const float4*)&sT[k * SXS + m0 + 4];
        float a[8] = {a0.x, a0.y, a0.z, a0.w, a1.x, a1.y, a1.z, a1.w};
#pragma unroll
        for (int m = 0; m < 8; m++) {
            acc[m][0] += a[m] * b4.x;
            acc[m][1] += a[m] * b4.y;
            acc[m][2] += a[m] * b4.z;
            acc[m][3] += a[m] * b4.w;
        }
    }
    __syncthreads();   // all reads of sT complete before overwriting
#pragma unroll
    for (int n = 0; n < 4; n++) {
        float4 lo = make_float4(acc[0][n], acc[1][n], acc[2][n], acc[3][n]);
        float4 hi = make_float4(acc[4][n], acc[5][n], acc[6][n], acc[7][n]);
        if (relu) {
            lo.x = fmaxf(lo.x, 0.f); lo.y = fmaxf(lo.y, 0.f);
            lo.z = fmaxf(lo.z, 0.f); lo.w = fmaxf(lo.w, 0.f);
            hi.x = fmaxf(hi.x, 0.f); hi.y = fmaxf(hi.y, 0.f);
            hi.z = fmaxf(hi.z, 0.f); hi.w = fmaxf(hi.w, 0.f);
        }
        int row = nt * 4 + n;
        *(float4*)&sT[row * SXS + m0]     = lo;
        *(float4*)&sT[row * SXS + m0 + 4] = hi;
    }
    __syncthreads();
}

// 48 -> 48 layer writing straight to global gout[node*48 + f] (with relu).
__device__ __forceinline__ void layer48_to_gmem(
    const float* sT, const float* __restrict__ W, const float* __restrict__ B,
    int tid, int base, float* __restrict__ gout, bool relu) {
    int mt = tid / 12, nt = tid % 12;
    int m0 = mt * 8;
    const float4* __restrict__ W4 = (const float4*)W;
    float4 bias = ((const float4*)B)[nt];

    float acc[8][4];
#pragma unroll
    for (int m = 0; m < 8; m++) {
        acc[m][0] = bias.x; acc[m][1] = bias.y;
        acc[m][2] = bias.z; acc[m][3] = bias.w;
    }
#pragma unroll 8
    for (int k = 0; k < HDIM; k++) {
        float4 b4 = W4[k * NQ + nt];
        float4 a0 = *(const float4*)&sT[k * SXS + m0];
        float4 a1 = *(const float4*)&sT[k * SXS + m0 + 4];
        float a[8] = {a0.x, a0.y, a0.z, a0.w, a1.x, a1.y, a1.z, a1.w};
#pragma unroll
        for (int m = 0; m < 8; m++) {
            acc[m][0] += a[m] * b4.x;
            acc[m][1] += a[m] * b4.y;
            acc[m][2] += a[m] * b4.z;
            acc[m][3] += a[m] * b4.w;
        }
    }
#pragma unroll
    for (int m = 0; m < 8; m++) {
        int node = base + m0 + m;
        if (node < N_NODES) {
            float4 v = make_float4(acc[m][0], acc[m][1], acc[m][2], acc[m][3]);
            if (relu) {
                v.x = fmaxf(v.x, 0.f); v.y = fmaxf(v.y, 0.f);
                v.z = fmaxf(v.z, 0.f); v.w = fmaxf(v.w, 0.f);
            }
            *(float4*)&gout[node * HDIM + nt * 4] = v;
        }
    }
}

// 48 -> 16 layer writing to global out[node*16 + f] (no relu). 128 active thr.
__device__ __forceinline__ void layer16_to_gmem(
    const float* sT, const float* __restrict__ W, const float* __restrict__ B,
    int tid, int base, float* __restrict__ out) {
    int mt = tid / 4, nt = tid % 4;   // mt 0..47, need mt < 32
    if (mt >= 32) return;
    int m0 = mt * 4;
    const float4* __restrict__ W4 = (const float4*)W;   // [48][4 float4 cols]
    float4 bias = ((const float4*)B)[nt];

    float acc[4][4];
#pragma unroll
    for (int m = 0; m < 4; m++) {
        acc[m][0] = bias.x; acc[m][1] = bias.y;
        acc[m][2] = bias.z; acc[m][3] = bias.w;
    }
#pragma unroll 8
    for (int k = 0; k < HDIM; k++) {
        float4 b4 = W4[k * 4 + nt];
        float4 a0 = *(const float4*)&sT[k * SXS + m0];
        float a[4] = {a0.x, a0.y, a0.z, a0.w};
#pragma unroll
        for (int m = 0; m < 4; m++) {
            acc[m][0] += a[m] * b4.x;
            acc[m][1] += a[m] * b4.y;
            acc[m][2] += a[m] * b4.z;
            acc[m][3] += a[m] * b4.w;
        }
    }
#pragma unroll
    for (int m = 0; m < 4; m++) {
        int node = base + m0 + m;
        if (node < N_NODES) {
            float4 v = make_float4(acc[m][0], acc[m][1], acc[m][2], acc[m][3]);
            *(float4*)&out[node * 16 + nt * 4] = v;
        }
    }
}

// Load 128-node tile of g_agg into sT transposed ([feat][node]).
__device__ __forceinline__ void load_tile(float* sT, int tid, int base) {
    const float4* __restrict__ in4 = (const float4*)g_agg;
    for (int i = tid; i < TM * NQ; i += MLP_THREADS) {
        int m = i % TM;          // consecutive threads -> consecutive columns
        int c = i / TM;
        int node = base + m;
        float4 v = make_float4(0.f, 0.f, 0.f, 0.f);
        if (node < N_NODES) v = in4[node * NQ + c];
        sT[(4 * c + 0) * SXS + m] = v.x;
        sT[(4 * c + 1) * SXS + m] = v.y;
        sT[(4 * c + 2) * SXS + m] = v.z;
        sT[(4 * c + 3) * SXS + m] = v.w;
    }
    __syncthreads();
}

// ---------------------------------------------------------------------------
// Conv MLP: g_agg -> relu(.W1+b1) -> relu(.W2+b2) -> g_h
// ---------------------------------------------------------------------------
__global__ __launch_bounds__(MLP_THREADS) void conv_mlp_kernel(
    const float* __restrict__ W1, const float* __restrict__ b1,
    const float* __restrict__ W2, const float* __restrict__ b2) {
    __shared__ float sT[HDIM * SXS];
    int tid = threadIdx.x;
    int base = blockIdx.x * TM;
    load_tile(sT, tid, base);
    layer48_to_smem(sT, W1, b1, tid, true);
    layer48_to_gmem(sT, W2, b2, tid, base, g_h, true);
}

// ---------------------------------------------------------------------------
// Final fused kernel: conv3 MLP + fc head (4 layers), writes d_out.
//   g_agg -> relu(W1)-> relu(W2) -> relu(Wf1) -> Wf2 -> out
// ---------------------------------------------------------------------------
__global__ __launch_bounds__(MLP_THREADS) void final_mlp_kernel(
    const float* __restrict__ W1, const float* __restrict__ b1,
    const float* __restrict__ W2, const float* __restrict__ b2,
    const float* __restrict__ W3, const float* __restrict__ b3,
    const float* __restrict__ W4, const float* __restrict__ b4,
    float* __restrict__ out) {
    __shared__ float sT[HDIM * SXS];
    int tid = threadIdx.x;
    int base = blockIdx.x * TM;
    load_tile(sT, tid, base);
    layer48_to_smem(sT, W1, b1, tid, true);   // conv3 layer 1
    layer48_to_smem(sT, W2, b2, tid, true);   // conv3 layer 2
    layer48_to_smem(sT, W3, b3, tid, true);   // fc1 + relu
    layer16_to_gmem(sT, W4, b4, tid, base, out);  // fc2 -> out
}

// ---------------------------------------------------------------------------
extern "C" void kernel_launch(void* const* d_in, const int* in_sizes, int n_in,
                              void* d_out, int out_size) {
    const float* x   = (const float*)d_in[0];
    const int*   ei  = (const int*)d_in[1];
    const float* w11 = (const float*)d_in[2];
    const float* b11 = (const float*)d_in[3];
    const float* w12 = (const float*)d_in[4];
    const float* b12 = (const float*)d_in[5];
    const float* w21 = (const float*)d_in[6];
    const float* b21 = (const float*)d_in[7];
    const float* w22 = (const float*)d_in[8];
    const float* b22 = (const float*)d_in[9];
    const float* w31 = (const float*)d_in[10];
    const float* b31 = (const float*)d_in[11];
    const float* w32 = (const float*)d_in[12];
    const float* b32 = (const float*)d_in[13];
    const float* wf1 = (const float*)d_in[14];
    const float* bf1 = (const float*)d_in[15];
    const float* wf2 = (const float*)d_in[16];
    const float* bf2 = (const float*)d_in[17];
    float* out = (float*)d_out;

    const int TPB = 256;
    const int init_grid   = (N_NODES * NQ + TPB - 1) / TPB;
    const int build_grid  = (E_EDGES + TPB - 1) / TPB;
    const int gather_grid = (N_NODES * NQ + TPB - 1) / TPB;
    const int mlp_grid    = (N_NODES + TM - 1) / TM;

    init_kernel<<<init_grid, TPB>>>(x);
    build_kernel<<<build_grid, TPB>>>(ei);   // adjacency built ONCE, reused x3

    // Conv 1
    gather_kernel<<<gather_grid, TPB>>>();
    conv_mlp_kernel<<<mlp_grid, MLP_THREADS>>>(w11, b11, w12, b12);
    // Conv 2
    gather_kernel<<<gather_grid, TPB>>>();
    conv_mlp_kernel<<<mlp_grid, MLP_THREADS>>>(w21, b21, w22, b22);
    // Conv 3 + head fused
    gather_kernel<<<gather_grid, TPB>>>();
    final_mlp_kernel<<<mlp_grid, MLP_THREADS>>>(w31, b31, w32, b32,
                                                wf1, bf1, wf2, bf2, out);

    (void)in_sizes; (void)n_in; (void)out_size;
}